// round 16
// baseline (speedup 1.0000x reference)
#include <cuda_runtime.h>
#include <cuda_fp16.h>
#include <math.h>
#include <stdint.h>

#define NLR  50000
#define EMBD 128
#define ENUM 800000

// ---------------- device scratch (no allocations allowed) ----------------
__device__ float  g_logits[(size_t)ENUM * 4];
__device__ __half g_xlh[(size_t)NLR * EMBD];
__device__ __half g_xrh[(size_t)NLR * EMBD];
__device__ __half g_lnh[(size_t)NLR * EMBD];
__device__ __half g_h1h[(size_t)NLR * EMBD];
__device__ __half g_wTh[128 * 768];          // wlT|wrT|weT|w1T(128x256)|w2T
__device__ int    g_cnt[NLR];
__device__ int    g_off[NLR + 1];
__device__ int    g_cur[NLR];
__device__ int    g_elist[ENUM];

#define WL_T 0
#define WR_T 16384
#define WE_T 32768
#define W1_T 49152
#define W2_T 81920

// ---------------- helpers ----------------
__device__ __forceinline__ void mma16(float c[4], const uint32_t a[4], const uint32_t b[2]) {
    asm volatile(
        "mma.sync.aligned.m16n8k16.row.col.f32.f16.f16.f32 "
        "{%0,%1,%2,%3},{%4,%5,%6,%7},{%8,%9},{%0,%1,%2,%3};\n"
        : "+f"(c[0]), "+f"(c[1]), "+f"(c[2]), "+f"(c[3])
        : "r"(a[0]), "r"(a[1]), "r"(a[2]), "r"(a[3]), "r"(b[0]), "r"(b[1]));
}
__device__ __forceinline__ void ldm4(uint32_t* r, uint32_t addr) {
    asm volatile("ldmatrix.sync.aligned.m8n8.x4.shared.b16 {%0,%1,%2,%3}, [%4];"
                 : "=r"(r[0]), "=r"(r[1]), "=r"(r[2]), "=r"(r[3]) : "r"(addr));
}
__device__ __forceinline__ void cp16(uint32_t saddr, const void* gptr, int sz) {
    asm volatile("cp.async.cg.shared.global [%0], [%1], 16, %2;\n"
                 :: "r"(saddr), "l"(gptr), "r"(sz));
}
__device__ __forceinline__ void cp_commit() { asm volatile("cp.async.commit_group;\n"); }
__device__ __forceinline__ void cp_wait1()  { asm volatile("cp.async.wait_group 1;\n"); }
__device__ __forceinline__ void cp_wait0()  { asm volatile("cp.async.wait_group 0;\n"); }
__device__ __forceinline__ uint32_t sa(const void* p) {
    return (uint32_t)__cvta_generic_to_shared(p);
}
__device__ __forceinline__ float4 ldcs4(const float* p) {
    return __ldcs((const float4*)p);
}

// ---- GEMM smem layout (64-row tiles): A 2x5120, B 2x10240, bias ----
#define GA_OFF 0
#define GB_OFF 10240
#define GBIAS  30720
#define SMEM_GEMM (GBIAS + 512)

// ---- edge kernel smem layout ----
#define EASH  0                     // 2 x 128 x 80B   (20480 B)
#define EBSH  20480                 // 2 x 128 x 80B   (20480 B)
#define EGATH 40960                 // 256 rows x 272B (69632 B)
#define EATT  110592                // 128 floats
#define ESRC  111104                // 128 ints
#define EDST  111616                // 128 ints
#define SMEM_EDGE2 112128
#define GSTR  136                   // gather row stride in halves (272 B)

// =================================================================
// one-time weight transpose + fp16 convert: g_wTh[n][k] = h(W[k][n])
// =================================================================
__global__ void transpose5(const float* __restrict__ Wl, const float* __restrict__ Wr,
                           const float* __restrict__ We, const float* __restrict__ W1,
                           const float* __restrict__ W2) {
    __shared__ float t[32][33];
    int b = blockIdx.x;
    const float* W; __half* out; int K;
    if      (b < 16) { W = Wl; out = g_wTh + WL_T; K = 128; }
    else if (b < 32) { W = Wr; out = g_wTh + WR_T; K = 128; b -= 16; }
    else if (b < 48) { W = We; out = g_wTh + WE_T; K = 128; b -= 32; }
    else if (b < 80) { W = W1; out = g_wTh + W1_T; K = 256; b -= 48; }
    else             { W = W2; out = g_wTh + W2_T; K = 128; b -= 80; }
    const int ktiles = K >> 5;
    const int k0 = (b % ktiles) * 32, n0 = (b / ktiles) * 32;
    const int tx = threadIdx.x, ty = threadIdx.y;
#pragma unroll
    for (int i = 0; i < 4; i++)
        t[ty + 8 * i][tx] = W[(size_t)(k0 + ty + 8 * i) * 128 + n0 + tx];
    __syncthreads();
#pragma unroll
    for (int i = 0; i < 4; i++)
        out[(size_t)(n0 + ty + 8 * i) * K + k0 + tx] = __float2half(t[tx][ty + 8 * i]);
}

// =================================================================
// GEMM body v16: 64-row tiles, 256 threads, 2x4 warp grid (32x32 warp
// tiles). Mixed A: chunks [0,nch1) = A1h fp16 via cp.async; chunks
// [nch1,nch) = A2f fp32 via LDG->cvt->STS. ldmatrix frags, 1 sync/chunk.
// =================================================================
template <bool HALF_OUT>
__device__ __forceinline__ void gemm_body(
    const __half* __restrict__ A1h, int K1,
    const float* __restrict__ A2f, int K2,
    const __half* __restrict__ BT, int Kb,
    const float* __restrict__ bias, float* __restrict__ C, __half* __restrict__ Ch,
    int M, int doRelu, int m0, char* smem_raw)
{
    const uint32_t sb = sa(smem_raw);
    float* bias_s = (float*)(smem_raw + GBIAS);

    const int tid = threadIdx.x;
    if (tid < 128) bias_s[tid] = bias[tid];

    const int warp = tid >> 5, lane = tid & 31;
    const int wm = warp & 1, wn = warp >> 1;     // 2x4 warp grid
    const int grp = lane >> 2, tg = lane & 3;

    const int nch1 = K1 >> 5;
    const int nch  = Kb >> 5;

    const int ar0 = tid >> 3, ac = (tid & 7) * 4;    // fp32 A: rows 0..31 (+32)
    const int hr0 = tid >> 2, hu = tid & 3;          // fp16 A: rows 0..63, 4 units
    float4 a0, a1;

    auto ldgAf = [&](int c) {   // fp32 chunks only
        if (c < nch1 || c >= nch) return;
        int ka = c * 32 - K1;
        int g0 = m0 + ar0, g1 = m0 + ar0 + 32;
        a0 = (g0 < M) ? *(const float4*)(A2f + (size_t)g0 * K2 + ka + ac)
                      : make_float4(0.f, 0.f, 0.f, 0.f);
        a1 = (g1 < M) ? *(const float4*)(A2f + (size_t)g1 * K2 + ka + ac)
                      : make_float4(0.f, 0.f, 0.f, 0.f);
    };
    auto stsAf = [&](int c, int buf) {
        if (c < nch1) return;
        char* base = smem_raw + GA_OFF + buf * 5120;
        __half2 h0 = __floats2half2_rn(a0.x, a0.y), h1 = __floats2half2_rn(a0.z, a0.w);
        *(uint2*)(base + ar0 * 80 + ac * 2) = make_uint2(*(uint32_t*)&h0, *(uint32_t*)&h1);
        __half2 h2 = __floats2half2_rn(a1.x, a1.y), h3 = __floats2half2_rn(a1.z, a1.w);
        *(uint2*)(base + (ar0 + 32) * 80 + ac * 2) = make_uint2(*(uint32_t*)&h2, *(uint32_t*)&h3);
    };
    auto stageAB = [&](int c, int buf) {  // cp.async: fp16 A (if applicable) + B
        if (c < nch1) {
            // 64 rows x 64B = 4KB, 256 thr x 16B
            int grow = m0 + hr0;
            int ok = (grow < M);
            cp16(sb + GA_OFF + buf * 5120 + hr0 * 80 + hu * 16,
                 A1h + (size_t)(ok ? grow : 0) * K1 + c * 32 + hu * 8, ok ? 16 : 0);
        }
        // B: 128 rows x 64B = 8KB, 256 thr x 2 x 16B
#pragma unroll
        for (int i = 0; i < 2; i++) {
            int slot = tid + i * 256;
            int r = slot >> 2, u = slot & 3;
            cp16(sb + GB_OFF + buf * 10240 + r * 80 + u * 16,
                 BT + (size_t)r * Kb + c * 32 + u * 8, 16);
        }
        cp_commit();
    };

    const uint32_t aOff = (uint32_t)(wm * 32 + (lane & 15)) * 80 + (uint32_t)((lane >> 4) << 3) * 2;
    const uint32_t bOff = (uint32_t)(wn * 32 + (lane & 7) + ((lane >> 4) << 3)) * 80
                        + (uint32_t)(((lane >> 3) & 1) << 3) * 2;

    float acc[2][4][4];
#pragma unroll
    for (int a = 0; a < 2; a++)
#pragma unroll
        for (int b = 0; b < 4; b++)
#pragma unroll
            for (int k = 0; k < 4; k++) acc[a][b][k] = 0.f;

    auto compute = [&](int buf) {
        const uint32_t ab = sb + GA_OFF + buf * 5120 + aOff;
        const uint32_t bb = sb + GB_OFF + buf * 10240 + bOff;
#pragma unroll
        for (int ks = 0; ks < 2; ks++) {
            const uint32_t ko = ks * 32;
            uint32_t bfr[8];
            ldm4(&bfr[0], bb + ko);
            ldm4(&bfr[4], bb + 1280 + ko);
            uint32_t afr[4];
            ldm4(afr, ab + ko);
            mma16(acc[0][0], afr, &bfr[0]);
            mma16(acc[0][1], afr, &bfr[2]);
            mma16(acc[0][2], afr, &bfr[4]);
            mma16(acc[0][3], afr, &bfr[6]);
            ldm4(afr, ab + 1280 + ko);
            mma16(acc[1][0], afr, &bfr[0]);
            mma16(acc[1][1], afr, &bfr[2]);
            mma16(acc[1][2], afr, &bfr[4]);
            mma16(acc[1][3], afr, &bfr[6]);
        }
    };

    // prologue
    ldgAf(0);
    stageAB(0, 0);
    stsAf(0, 0);
    ldgAf(1);

    for (int c = 0; c < nch; c++) {
        const int buf = c & 1;
        cp_wait0();
        __syncthreads();
        if (c + 1 < nch) stageAB(c + 1, buf ^ 1);
        compute(buf);
        if (c + 1 < nch) {
            stsAf(c + 1, buf ^ 1);
            ldgAf(c + 2);
        }
    }

#pragma unroll
    for (int mt = 0; mt < 2; mt++) {
#pragma unroll
        for (int half = 0; half < 2; half++) {
            int grow = m0 + wm * 32 + mt * 16 + half * 8 + grp;
            if (grow < M) {
#pragma unroll
                for (int nt = 0; nt < 4; nt++) {
                    int cc = wn * 32 + nt * 8 + tg * 2;
                    float v0 = acc[mt][nt][half * 2 + 0] + bias_s[cc];
                    float v1 = acc[mt][nt][half * 2 + 1] + bias_s[cc + 1];
                    if (doRelu) { v0 = fmaxf(v0, 0.f); v1 = fmaxf(v1, 0.f); }
                    if (HALF_OUT) {
                        __half2 h = __floats2half2_rn(v0, v1);
                        *(__half2*)(Ch + (size_t)grow * 128 + cc) = h;
                    } else {
                        float2 o; o.x = v0; o.y = v1;
                        *(float2*)(C + (size_t)grow * 128 + cc) = o;
                    }
                }
            }
        }
    }
}

__global__ __launch_bounds__(256, 4) void gemm128f(
    const __half* __restrict__ A1h, int K1,
    const float* __restrict__ A2f, int K2,
    const __half* __restrict__ BT, int Kb,
    const float* __restrict__ bias, float* __restrict__ C, int M, int doRelu)
{
    extern __shared__ char smem_raw[];
    gemm_body<false>(A1h, K1, A2f, K2, BT, Kb, bias, C, nullptr, M, doRelu,
                     blockIdx.x * 64, smem_raw);
}

__global__ __launch_bounds__(256, 4) void gemm128h(
    const __half* __restrict__ A1h, int K1,
    const float* __restrict__ A2f, int K2,
    const __half* __restrict__ BT, int Kb,
    const float* __restrict__ bias, __half* __restrict__ Ch, int M, int doRelu)
{
    extern __shared__ char smem_raw[];
    gemm_body<true>(A1h, K1, A2f, K2, BT, Kb, bias, nullptr, Ch, M, doRelu,
                    blockIdx.x * 64, smem_raw);
}

// node projections merged, half output to g_xlh / g_xrh
__global__ __launch_bounds__(256, 4) void gemm_dual(
    const float* __restrict__ Aa, const __half* __restrict__ BTa,
    const float* __restrict__ ba,
    const float* __restrict__ Ab, const __half* __restrict__ BTb,
    const float* __restrict__ bb,
    int M, int half)
{
    extern __shared__ char smem_raw[];
    if (blockIdx.x < half)
        gemm_body<true>(nullptr, 0, Aa, 128, BTa, 128, ba, nullptr, g_xlh, M, 0,
                        blockIdx.x * 64, smem_raw);
    else
        gemm_body<true>(nullptr, 0, Ab, 128, BTb, 128, bb, nullptr, g_xrh, M, 0,
                        (blockIdx.x - half) * 64, smem_raw);
}

// =================================================================
// Edge kernel (R13, unchanged): ldmatrix fragments, single sync/chunk,
// cp.async smem-staged xl/xr gathers, __ldcs streaming EF loads.
// =================================================================
__global__ __launch_bounds__(512, 2) void edge_logits_kernel(
    const float* __restrict__ EF, const __half* __restrict__ WeT,
    const int* __restrict__ src, const int* __restrict__ dst,
    const float* __restrict__ att)
{
    extern __shared__ char smem[];
    const uint32_t sb = sa(smem);
    float* att_s = (float*)(smem + EATT);
    int*   src_s = (int*)(smem + ESRC);
    int*   dst_s = (int*)(smem + EDST);
    const __half* gath = (const __half*)(smem + EGATH);

    const int tid = threadIdx.x;
    const int e0  = blockIdx.x * 128;
    const int warp = tid >> 5, lane = tid & 31;
    const int wm = warp & 3, wn = warp >> 2;
    const int grp = lane >> 2, tg = lane & 3;

    if (tid < 128) {
        src_s[tid] = src[e0 + tid];
        dst_s[tid] = dst[e0 + tid];
        att_s[tid] = att[tid];
    }

    const int ar0 = tid >> 3, ac = (tid & 7) * 4;
    float4 a0, a1;
    auto ldgA = [&](int c) {
        const int ka = c * 32;
        a0 = ldcs4(EF + (size_t)(e0 + ar0) * 128 + ka + ac);
        a1 = ldcs4(EF + (size_t)(e0 + ar0 + 64) * 128 + ka + ac);
    };
    auto stsA = [&](int buf) {
        char* base = smem + EASH + buf * 10240;
        __half2 h0 = __floats2half2_rn(a0.x, a0.y), h1 = __floats2half2_rn(a0.z, a0.w);
        *(uint2*)(base + ar0 * 80 + ac * 2) = make_uint2(*(uint32_t*)&h0, *(uint32_t*)&h1);
        __half2 h2 = __floats2half2_rn(a1.x, a1.y), h3 = __floats2half2_rn(a1.z, a1.w);
        *(uint2*)(base + (ar0 + 64) * 80 + ac * 2) = make_uint2(*(uint32_t*)&h2, *(uint32_t*)&h3);
    };
    const int br = tid >> 2, bu = (tid & 3) * 8;
    auto stageB = [&](int c, int buf) {
        cp16(sb + EBSH + buf * 10240 + br * 80 + bu * 2,
             WeT + (size_t)br * 128 + c * 32 + bu, 16);
        cp_commit();
    };

    const uint32_t aOff = (uint32_t)(wm * 32 + (lane & 15)) * 80 + (uint32_t)((lane >> 4) << 3) * 2;
    const uint32_t bOff = (uint32_t)(wn * 32 + (lane & 7) + ((lane >> 4) << 3)) * 80
                        + (uint32_t)(((lane >> 3) & 1) << 3) * 2;

    float acc[2][4][4];
#pragma unroll
    for (int a = 0; a < 2; a++)
#pragma unroll
        for (int b = 0; b < 4; b++)
#pragma unroll
            for (int k = 0; k < 4; k++) acc[a][b][k] = 0.f;

    auto compute = [&](int buf) {
        const uint32_t ab = sb + EASH + buf * 10240 + aOff;
        const uint32_t bb = sb + EBSH + buf * 10240 + bOff;
#pragma unroll
        for (int ks = 0; ks < 2; ks++) {
            const uint32_t ko = ks * 32;
            uint32_t bfr[8];
            ldm4(&bfr[0], bb + ko);
            ldm4(&bfr[4], bb + 1280 + ko);
            uint32_t afr[4];
            ldm4(afr, ab + ko);
            mma16(acc[0][0], afr, &bfr[0]);
            mma16(acc[0][1], afr, &bfr[2]);
            mma16(acc[0][2], afr, &bfr[4]);
            mma16(acc[0][3], afr, &bfr[6]);
            ldm4(afr, ab + 1280 + ko);
            mma16(acc[1][0], afr, &bfr[0]);
            mma16(acc[1][1], afr, &bfr[2]);
            mma16(acc[1][2], afr, &bfr[4]);
            mma16(acc[1][3], afr, &bfr[6]);
        }
    };

    // ---- prologue ----
    ldgA(0);
    stageB(0, 0);
    stsA(0);
    ldgA(1);

    // chunk 0
    cp_wait0();
    __syncthreads();
    stageB(1, 1);
    {
#pragma unroll
        for (int j = 0; j < 8; j++) {
            int s = tid + 512 * j;
            int row = s >> 4, u = s & 15;
            int idx = row & 127;
            const __half* gp = (j < 4)
                ? g_xlh + (size_t)src_s[idx] * 128 + u * 8
                : g_xrh + (size_t)dst_s[idx] * 128 + u * 8;
            cp16(sb + EGATH + row * 272 + u * 16, gp, 16);
        }
        cp_commit();
    }
    compute(0);
    stsA(1); ldgA(2);

    // chunk 1
    cp_wait1();
    __syncthreads();
    stageB(2, 0);
    compute(1);
    stsA(0); ldgA(3);

    // chunk 2
    cp_wait0();
    __syncthreads();
    stageB(3, 1);
    compute(0);
    stsA(1);

    // chunk 3
    cp_wait0();
    __syncthreads();
    compute(1);

    // ---- epilogue ----
#pragma unroll
    for (int mt = 0; mt < 2; mt++) {
#pragma unroll
        for (int half = 0; half < 2; half++) {
            int row = wm * 32 + mt * 16 + half * 8 + grp;
            const __half* xl = gath + (size_t)row * GSTR;
            const __half* xr = gath + (size_t)(128 + row) * GSTR;
            float partial = 0.f;
#pragma unroll
            for (int nt = 0; nt < 4; nt++) {
                int col = wn * 32 + nt * 8 + tg * 2;
                float2 a = __half22float2(*(const __half2*)(xl + col));
                float2 b = __half22float2(*(const __half2*)(xr + col));
                float z0 = acc[mt][nt][half * 2 + 0] + a.x + b.x;
                float z1 = acc[mt][nt][half * 2 + 1] + a.y + b.y;
                z0 = (z0 > 0.f) ? z0 : 0.2f * z0;
                z1 = (z1 > 0.f) ? z1 : 0.2f * z1;
                partial += z0 * att_s[col] + z1 * att_s[col + 1];
            }
            partial += __shfl_xor_sync(0xFFFFFFFFu, partial, 1);
            partial += __shfl_xor_sync(0xFFFFFFFFu, partial, 2);
            if (tg == 0)
                g_logits[(size_t)(e0 + row) * 4 + wn] = partial;
        }
    }
}

// ---------------- CSR build ----------------
__global__ void count_kernel(const int* __restrict__ dst) {
    int e = blockIdx.x * blockDim.x + threadIdx.x;
    if (e < ENUM) atomicAdd(&g_cnt[dst[e]], 1);
}

__global__ __launch_bounds__(1024) void scan_kernel() {
    __shared__ int part[1024];
    const int t = threadIdx.x;
    const int CH = (NLR + 1023) / 1024;
    int start = t * CH, end = min(start + CH, NLR);
    int s = 0;
    for (int i = start; i < end; i++) s += g_cnt[i];
    part[t] = s;
    __syncthreads();
    for (int off = 1; off < 1024; off <<= 1) {
        int v = (t >= off) ? part[t - off] : 0;
        __syncthreads();
        part[t] += v;
        __syncthreads();
    }
    int run = part[t] - s;
    for (int i = start; i < end; i++) {
        g_off[i] = run; g_cur[i] = run;
        run += g_cnt[i];
    }
    if (t == 1023) g_off[NLR] = part[1023];
}

__global__ void fill_kernel(const int* __restrict__ dst) {
    int e = blockIdx.x * blockDim.x + threadIdx.x;
    if (e < ENUM) {
        int p = atomicAdd(&g_cur[dst[e]], 1);
        g_elist[p] = e;
    }
}

// =================================================================
// Warp-per-node fused segment softmax + message + b_conv + LayerNorm.
// Gather loop unrolled by 2; fp16 output to g_lnh.
// =================================================================
__global__ __launch_bounds__(256) void message_ln_kernel(
    const int* __restrict__ src,
    const float* __restrict__ bconv,
    const float* __restrict__ lng, const float* __restrict__ lnb)
{
    const int node = (blockIdx.x * blockDim.x + threadIdx.x) >> 5;
    const int lane = threadIdx.x & 31;
    if (node >= NLR) return;

    const int h  = lane >> 3;
    const int c4 = lane * 4;
    const int off0 = g_off[node];
    const int deg  = g_off[node + 1] - off0;

    float4 mx = make_float4(-1e30f, -1e30f, -1e30f, -1e30f);
    for (int i = lane; i < deg; i += 32) {
        int e = __ldg(&g_elist[off0 + i]);
        float4 lg = *(const float4*)&g_logits[(size_t)e * 4];
        mx.x = fmaxf(mx.x, lg.x); mx.y = fmaxf(mx.y, lg.y);
        mx.z = fmaxf(mx.z, lg.z); mx.w = fmaxf(mx.w, lg.w);
    }
#pragma unroll
    for (int o = 16; o; o >>= 1) {
        mx.x = fmaxf(mx.x, __shfl_xor_sync(0xFFFFFFFFu, mx.x, o));
        mx.y = fmaxf(mx.y, __shfl_xor_sync(0xFFFFFFFFu, mx.y, o));
        mx.z = fmaxf(mx.z, __shfl_xor_sync(0xFFFFFFFFu, mx.z, o));
        mx.w = fmaxf(mx.w, __shfl_xor_sync(0xFFFFFFFFu, mx.w, o));
    }

    float4 sm = make_float4(0.f, 0.f, 0.f, 0.f);
    for (int i = lane; i < deg; i += 32) {
        int e = __ldg(&g_elist[off0 + i]);
        float4 lg = *(const float4*)&g_logits[(size_t)e * 4];
        sm.x += __expf(lg.x - mx.x); sm.y += __expf(lg.y - mx.y);
        sm.z += __expf(lg.z - mx.z); sm.w += __expf(lg.w - mx.w);
    }
#pragma unroll
    for (int o = 16; o; o >>= 1) {
        sm.x += __shfl_xor_sync(0xFFFFFFFFu, sm.x, o);
        sm.y += __shfl_xor_sync(0xFFFFFFFFu, sm.y, o);
        sm.z += __shfl_xor_sync(0xFFFFFFFFu, sm.z, o);
        sm.w += __shfl_xor_sync(0xFFFFFFFFu, sm.w, o);
    }

    const float m_h = (h == 0) ? mx.x : (h == 1) ? mx.y : (h == 2) ? mx.z : mx.w;
    const float s_h = (h == 0) ? sm.x : (h == 1) ? sm.y : (h == 2) ? sm.z : sm.w;
    const float inv_h = 1.f / (s_h + 1e-16f);

    float4 acc = make_float4(0.f, 0.f, 0.f, 0.f);
    int j = 0;
    for (; j + 1 < deg; j += 2) {      // unroll-by-2: two independent chains
        int e0v = __ldg(&g_elist[off0 + j]);
        int e1v = __ldg(&g_elist[off0 + j + 1]);
        int s0 = __ldg(&src[e0v]);
        int s1 = __ldg(&src[e1v]);
        float a0 = __expf(__ldg(&g_logits[(size_t)e0v * 4 + h]) - m_h);
        float a1 = __expf(__ldg(&g_logits[(size_t)e1v * 4 + h]) - m_h);
        const __half2* x0 = (const __half2*)(g_xlh + (size_t)s0 * 128 + c4);
        const __half2* x1 = (const __half2*)(g_xlh + (size_t)s1 * 128 + c4);
        float2 p00 = __half22float2(x0[0]), p01 = __half22float2(x0[1]);
        float2 p10 = __half22float2(x1[0]), p11 = __half22float2(x1[1]);
        acc.x = fmaf(a0, p00.x, fmaf(a1, p10.x, acc.x));
        acc.y = fmaf(a0, p00.y, fmaf(a1, p10.y, acc.y));
        acc.z = fmaf(a0, p01.x, fmaf(a1, p11.x, acc.z));
        acc.w = fmaf(a0, p01.y, fmaf(a1, p11.y, acc.w));
    }
    if (j < deg) {
        int e = __ldg(&g_elist[off0 + j]);
        int sr = __ldg(&src[e]);
        float a = __expf(__ldg(&g_logits[(size_t)e * 4 + h]) - m_h);
        const __half2* xp = (const __half2*)(g_xlh + (size_t)sr * 128 + c4);
        float2 x01 = __half22float2(xp[0]);
        float2 x23 = __half22float2(xp[1]);
        acc.x = fmaf(a, x01.x, acc.x); acc.y = fmaf(a, x01.y, acc.y);
        acc.z = fmaf(a, x23.x, acc.z); acc.w = fmaf(a, x23.y, acc.w);
    }
    float4 bc = *(const float4*)&bconv[c4];
    float4 msg;
    msg.x = acc.x * inv_h + bc.x; msg.y = acc.y * inv_h + bc.y;
    msg.z = acc.z * inv_h + bc.z; msg.w = acc.w * inv_h + bc.w;

    float s1 = msg.x + msg.y + msg.z + msg.w;
    float s2 = msg.x * msg.x + msg.y * msg.y + msg.z * msg.z + msg.w * msg.w;
#pragma unroll
    for (int o = 16; o; o >>= 1) {
        s1 += __shfl_xor_sync(0xFFFFFFFFu, s1, o);
        s2 += __shfl_xor_sync(0xFFFFFFFFu, s2, o);
    }
    float mu  = s1 * (1.f / 128.f);
    float var = fmaxf(s2 * (1.f / 128.f) - mu * mu, 0.f);
    float r = rsqrtf(var + 1e-5f);

    float4 g = *(const float4*)&lng[c4];
    float4 b = *(const float4*)&lnb[c4];
    __half2 o0 = __floats2half2_rn((msg.x - mu) * r * g.x + b.x,
                                   (msg.y - mu) * r * g.y + b.y);
    __half2 o1 = __floats2half2_rn((msg.z - mu) * r * g.z + b.z,
                                   (msg.w - mu) * r * g.w + b.w);
    *(uint2*)&g_lnh[(size_t)node * 128 + c4] =
        make_uint2(*(uint32_t*)&o0, *(uint32_t*)&o1);
}

// =================================================================
extern "C" void kernel_launch(void* const* d_in, const int* in_sizes, int n_in,
                              void* d_out, int out_size) {
    const float* left  = (const float*)d_in[0];
    const int*   eidx  = (const int*)d_in[1];
    const float* ef    = (const float*)d_in[2];
    const float* right = (const float*)d_in[3];
    const float* W_l   = (const float*)d_in[4];
    const float* b_l   = (const float*)d_in[5];
    const float* W_r   = (const float*)d_in[6];
    const float* b_r   = (const float*)d_in[7];
    const float* W_e   = (const float*)d_in[8];
    const float* att   = (const float*)d_in[9];
    const float* bconv = (const float*)d_in[10];
    const float* ln_g  = (const float*)d_in[11];
    const float* ln_b  = (const float*)d_in[12];
    const float* W1    = (const float*)d_in[13];
    const float* b1    = (const float*)d_in[14];
    const float* W2    = (const float*)d_in[15];
    const float* b2    = (const float*)d_in[16];
    float* out = (float*)d_out;

    const int* src = eidx;
    const int* dst = eidx + ENUM;

    __half* lnh; cudaGetSymbolAddress((void**)&lnh, g_lnh);
    __half* h1h; cudaGetSymbolAddress((void**)&h1h, g_h1h);
    __half* wTh; cudaGetSymbolAddress((void**)&wTh, g_wTh);
    int*    cnt; cudaGetSymbolAddress((void**)&cnt, g_cnt);

    cudaFuncSetAttribute(gemm128f,
                         cudaFuncAttributeMaxDynamicSharedMemorySize, SMEM_GEMM);
    cudaFuncSetAttribute(gemm128h,
                         cudaFuncAttributeMaxDynamicSharedMemorySize, SMEM_GEMM);
    cudaFuncSetAttribute(gemm_dual,
                         cudaFuncAttributeMaxDynamicSharedMemorySize, SMEM_GEMM);
    cudaFuncSetAttribute(edge_logits_kernel,
                         cudaFuncAttributeMaxDynamicSharedMemorySize, SMEM_EDGE2);

    const int gblk = (NLR + 63) / 64;   // 782 (64-row tiles)

    // side stream for the CSR branch (independent of the GEMM chain)
    cudaStream_t s2;
    cudaStreamCreateWithFlags(&s2, cudaStreamNonBlocking);
    cudaEvent_t evFork, evJoin;
    cudaEventCreateWithFlags(&evFork, cudaEventDisableTiming);
    cudaEventCreateWithFlags(&evJoin, cudaEventDisableTiming);

    cudaEventRecord(evFork, 0);
    cudaStreamWaitEvent(s2, evFork, 0);

    cudaMemsetAsync(cnt, 0, NLR * sizeof(int), s2);

    transpose5<<<96, dim3(32, 8)>>>(W_l, W_r, W_e, W1, W2);                  // k1
    count_kernel<<<(ENUM + 255) / 256, 256, 0, s2>>>(dst);                   // k2
    gemm_dual<<<2 * gblk, 256, SMEM_GEMM>>>(left, wTh + WL_T, b_l,
                                            right, wTh + WR_T, b_r,
                                            NLR, gblk);                      // k3
    edge_logits_kernel<<<ENUM / 128, 512, SMEM_EDGE2>>>(ef, wTh + WE_T,
                                                        src, dst, att);      // k4 (profiled)
    scan_kernel<<<1, 1024, 0, s2>>>();                                       // k5
    fill_kernel<<<(ENUM + 255) / 256, 256, 0, s2>>>(dst);                    // k6

    cudaEventRecord(evJoin, s2);
    cudaStreamWaitEvent(0, evJoin, 0);

    message_ln_kernel<<<(NLR * 32 + 255) / 256, 256>>>(src, bconv, ln_g, ln_b); // k7
    // mlp1: h1 = relu([ln(fp16) | right(fp32)] @ W1 + b1) -> fp16
    gemm128h<<<gblk, 256, SMEM_GEMM>>>(lnh, 128, right, 128, wTh + W1_T, 256,
                                       b1, h1h, NLR, 1);                     // k8
    // mlp2: out = h1(fp16) @ W2 + b2 -> fp32
    gemm128f<<<gblk, 256, SMEM_GEMM>>>(h1h, 128, nullptr, 0, wTh + W2_T, 128,
                                       b2, out, NLR, 0);                     // k9
}

// round 17
// speedup vs baseline: 1.0150x; 1.0150x over previous
#include <cuda_runtime.h>
#include <cuda_fp16.h>
#include <math.h>
#include <stdint.h>

#define NLR  50000
#define EMBD 128
#define ENUM 800000

// ---------------- device scratch (no allocations allowed) ----------------
__device__ float  g_logits[(size_t)ENUM * 4];
__device__ __half g_xlh[(size_t)NLR * EMBD];
__device__ __half g_xrh[(size_t)NLR * EMBD];
__device__ __half g_lnh[(size_t)NLR * EMBD];
__device__ __half g_wTh[128 * 768];          // wlT|wrT|weT|w1T(128x256)|w2T
__device__ int    g_cnt[NLR];
__device__ int    g_off[NLR + 1];
__device__ int    g_cur[NLR];
__device__ int    g_elist[ENUM];

#define WL_T 0
#define WR_T 16384
#define WE_T 32768
#define W1_T 49152
#define W2_T 81920

// ---------------- helpers ----------------
__device__ __forceinline__ void mma16(float c[4], const uint32_t a[4], const uint32_t b[2]) {
    asm volatile(
        "mma.sync.aligned.m16n8k16.row.col.f32.f16.f16.f32 "
        "{%0,%1,%2,%3},{%4,%5,%6,%7},{%8,%9},{%0,%1,%2,%3};\n"
        : "+f"(c[0]), "+f"(c[1]), "+f"(c[2]), "+f"(c[3])
        : "r"(a[0]), "r"(a[1]), "r"(a[2]), "r"(a[3]), "r"(b[0]), "r"(b[1]));
}
__device__ __forceinline__ void ldm4(uint32_t* r, uint32_t addr) {
    asm volatile("ldmatrix.sync.aligned.m8n8.x4.shared.b16 {%0,%1,%2,%3}, [%4];"
                 : "=r"(r[0]), "=r"(r[1]), "=r"(r[2]), "=r"(r[3]) : "r"(addr));
}
__device__ __forceinline__ void cp16(uint32_t saddr, const void* gptr, int sz) {
    asm volatile("cp.async.cg.shared.global [%0], [%1], 16, %2;\n"
                 :: "r"(saddr), "l"(gptr), "r"(sz));
}
__device__ __forceinline__ void cp_commit() { asm volatile("cp.async.commit_group;\n"); }
__device__ __forceinline__ void cp_wait1()  { asm volatile("cp.async.wait_group 1;\n"); }
__device__ __forceinline__ void cp_wait0()  { asm volatile("cp.async.wait_group 0;\n"); }
__device__ __forceinline__ uint32_t sa(const void* p) {
    return (uint32_t)__cvta_generic_to_shared(p);
}
__device__ __forceinline__ float4 ldcs4(const float* p) {
    return __ldcs((const float4*)p);
}

// ---- GEMM smem layout (64-row tiles): A 2x5120, B 2x10240, bias ----
#define GA_OFF 0
#define GB_OFF 10240
#define GBIAS  30720
#define SMEM_GEMM (GBIAS + 512)

// ---- fused MLP smem layout ----
#define FA_OFF 0                    // A staging: 2 x 5120
#define FB_OFF 10240                // B staging: 2 x 10240
#define FH_OFF 30720                // h1: 4 chunks x 64 rows x 80B
#define FBIAS  51200                // b1[128] + b2[128] floats
#define SMEM_FUSED (FBIAS + 1024)   // 52224

// ---- edge kernel smem layout ----
#define EASH  0                     // 2 x 128 x 80B   (20480 B)
#define EBSH  20480                 // 2 x 128 x 80B   (20480 B)
#define EGATH 40960                 // 256 rows x 272B (69632 B)
#define EATT  110592                // 128 floats
#define ESRC  111104                // 128 ints
#define EDST  111616                // 128 ints
#define SMEM_EDGE2 112128
#define GSTR  136                   // gather row stride in halves (272 B)

// =================================================================
// one-time weight transpose + fp16 convert: g_wTh[n][k] = h(W[k][n])
// =================================================================
__global__ void transpose5(const float* __restrict__ Wl, const float* __restrict__ Wr,
                           const float* __restrict__ We, const float* __restrict__ W1,
                           const float* __restrict__ W2) {
    __shared__ float t[32][33];
    int b = blockIdx.x;
    const float* W; __half* out; int K;
    if      (b < 16) { W = Wl; out = g_wTh + WL_T; K = 128; }
    else if (b < 32) { W = Wr; out = g_wTh + WR_T; K = 128; b -= 16; }
    else if (b < 48) { W = We; out = g_wTh + WE_T; K = 128; b -= 32; }
    else if (b < 80) { W = W1; out = g_wTh + W1_T; K = 256; b -= 48; }
    else             { W = W2; out = g_wTh + W2_T; K = 128; b -= 80; }
    const int ktiles = K >> 5;
    const int k0 = (b % ktiles) * 32, n0 = (b / ktiles) * 32;
    const int tx = threadIdx.x, ty = threadIdx.y;
#pragma unroll
    for (int i = 0; i < 4; i++)
        t[ty + 8 * i][tx] = W[(size_t)(k0 + ty + 8 * i) * 128 + n0 + tx];
    __syncthreads();
#pragma unroll
    for (int i = 0; i < 4; i++)
        out[(size_t)(n0 + ty + 8 * i) * K + k0 + tx] = __float2half(t[tx][ty + 8 * i]);
}

// =================================================================
// GEMM body (64-row tiles, 256 thr, 2x4 warps). Mixed A sources.
// Used for the node projections (gemm_dual).
// =================================================================
template <bool HALF_OUT>
__device__ __forceinline__ void gemm_body(
    const __half* __restrict__ A1h, int K1,
    const float* __restrict__ A2f, int K2,
    const __half* __restrict__ BT, int Kb,
    const float* __restrict__ bias, float* __restrict__ C, __half* __restrict__ Ch,
    int M, int doRelu, int m0, char* smem_raw)
{
    const uint32_t sb = sa(smem_raw);
    float* bias_s = (float*)(smem_raw + GBIAS);

    const int tid = threadIdx.x;
    if (tid < 128) bias_s[tid] = bias[tid];

    const int warp = tid >> 5, lane = tid & 31;
    const int wm = warp & 1, wn = warp >> 1;
    const int grp = lane >> 2, tg = lane & 3;

    const int nch1 = K1 >> 5;
    const int nch  = Kb >> 5;

    const int ar0 = tid >> 3, ac = (tid & 7) * 4;
    const int hr0 = tid >> 2, hu = tid & 3;
    float4 a0, a1;

    auto ldgAf = [&](int c) {
        if (c < nch1 || c >= nch) return;
        int ka = c * 32 - K1;
        int g0 = m0 + ar0, g1 = m0 + ar0 + 32;
        a0 = (g0 < M) ? *(const float4*)(A2f + (size_t)g0 * K2 + ka + ac)
                      : make_float4(0.f, 0.f, 0.f, 0.f);
        a1 = (g1 < M) ? *(const float4*)(A2f + (size_t)g1 * K2 + ka + ac)
                      : make_float4(0.f, 0.f, 0.f, 0.f);
    };
    auto stsAf = [&](int c, int buf) {
        if (c < nch1) return;
        char* base = smem_raw + GA_OFF + buf * 5120;
        __half2 h0 = __floats2half2_rn(a0.x, a0.y), h1 = __floats2half2_rn(a0.z, a0.w);
        *(uint2*)(base + ar0 * 80 + ac * 2) = make_uint2(*(uint32_t*)&h0, *(uint32_t*)&h1);
        __half2 h2 = __floats2half2_rn(a1.x, a1.y), h3 = __floats2half2_rn(a1.z, a1.w);
        *(uint2*)(base + (ar0 + 32) * 80 + ac * 2) = make_uint2(*(uint32_t*)&h2, *(uint32_t*)&h3);
    };
    auto stageAB = [&](int c, int buf) {
        if (c < nch1) {
            int grow = m0 + hr0;
            int ok = (grow < M);
            cp16(sb + GA_OFF + buf * 5120 + hr0 * 80 + hu * 16,
                 A1h + (size_t)(ok ? grow : 0) * K1 + c * 32 + hu * 8, ok ? 16 : 0);
        }
#pragma unroll
        for (int i = 0; i < 2; i++) {
            int slot = tid + i * 256;
            int r = slot >> 2, u = slot & 3;
            cp16(sb + GB_OFF + buf * 10240 + r * 80 + u * 16,
                 BT + (size_t)r * Kb + c * 32 + u * 8, 16);
        }
        cp_commit();
    };

    const uint32_t aOff = (uint32_t)(wm * 32 + (lane & 15)) * 80 + (uint32_t)((lane >> 4) << 3) * 2;
    const uint32_t bOff = (uint32_t)(wn * 32 + (lane & 7) + ((lane >> 4) << 3)) * 80
                        + (uint32_t)(((lane >> 3) & 1) << 3) * 2;

    float acc[2][4][4];
#pragma unroll
    for (int a = 0; a < 2; a++)
#pragma unroll
        for (int b = 0; b < 4; b++)
#pragma unroll
            for (int k = 0; k < 4; k++) acc[a][b][k] = 0.f;

    auto compute = [&](int buf) {
        const uint32_t ab = sb + GA_OFF + buf * 5120 + aOff;
        const uint32_t bb = sb + GB_OFF + buf * 10240 + bOff;
#pragma unroll
        for (int ks = 0; ks < 2; ks++) {
            const uint32_t ko = ks * 32;
            uint32_t bfr[8];
            ldm4(&bfr[0], bb + ko);
            ldm4(&bfr[4], bb + 1280 + ko);
            uint32_t afr[4];
            ldm4(afr, ab + ko);
            mma16(acc[0][0], afr, &bfr[0]);
            mma16(acc[0][1], afr, &bfr[2]);
            mma16(acc[0][2], afr, &bfr[4]);
            mma16(acc[0][3], afr, &bfr[6]);
            ldm4(afr, ab + 1280 + ko);
            mma16(acc[1][0], afr, &bfr[0]);
            mma16(acc[1][1], afr, &bfr[2]);
            mma16(acc[1][2], afr, &bfr[4]);
            mma16(acc[1][3], afr, &bfr[6]);
        }
    };

    ldgAf(0);
    stageAB(0, 0);
    stsAf(0, 0);
    ldgAf(1);

    for (int c = 0; c < nch; c++) {
        const int buf = c & 1;
        cp_wait0();
        __syncthreads();
        if (c + 1 < nch) stageAB(c + 1, buf ^ 1);
        compute(buf);
        if (c + 1 < nch) {
            stsAf(c + 1, buf ^ 1);
            ldgAf(c + 2);
        }
    }

#pragma unroll
    for (int mt = 0; mt < 2; mt++) {
#pragma unroll
        for (int half = 0; half < 2; half++) {
            int grow = m0 + wm * 32 + mt * 16 + half * 8 + grp;
            if (grow < M) {
#pragma unroll
                for (int nt = 0; nt < 4; nt++) {
                    int cc = wn * 32 + nt * 8 + tg * 2;
                    float v0 = acc[mt][nt][half * 2 + 0] + bias_s[cc];
                    float v1 = acc[mt][nt][half * 2 + 1] + bias_s[cc + 1];
                    if (doRelu) { v0 = fmaxf(v0, 0.f); v1 = fmaxf(v1, 0.f); }
                    if (HALF_OUT) {
                        __half2 h = __floats2half2_rn(v0, v1);
                        *(__half2*)(Ch + (size_t)grow * 128 + cc) = h;
                    } else {
                        float2 o; o.x = v0; o.y = v1;
                        *(float2*)(C + (size_t)grow * 128 + cc) = o;
                    }
                }
            }
        }
    }
}

// node projections merged, half output to g_xlh / g_xrh
__global__ __launch_bounds__(256, 4) void gemm_dual(
    const float* __restrict__ Aa, const __half* __restrict__ BTa,
    const float* __restrict__ ba,
    const float* __restrict__ Ab, const __half* __restrict__ BTb,
    const float* __restrict__ bb,
    int M, int half)
{
    extern __shared__ char smem_raw[];
    if (blockIdx.x < half)
        gemm_body<true>(nullptr, 0, Aa, 128, BTa, 128, ba, nullptr, g_xlh, M, 0,
                        blockIdx.x * 64, smem_raw);
    else
        gemm_body<true>(nullptr, 0, Ab, 128, BTb, 128, bb, nullptr, g_xrh, M, 0,
                        (blockIdx.x - half) * 64, smem_raw);
}

// =================================================================
// Fused MLP: per 64-row tile,
//   phase 1: h1 = relu([lnh(fp16)|right(fp32)] @ W1^T + b1) -> smem
//   phase 2: out = h1 @ W2^T + b2 -> global fp32
// =================================================================
__global__ __launch_bounds__(256, 4) void mlp_fused(
    const __half* __restrict__ LNH, const float* __restrict__ RIGHT,
    const __half* __restrict__ W1T, const __half* __restrict__ W2T,
    const float* __restrict__ b1, const float* __restrict__ b2,
    float* __restrict__ OUT, int M)
{
    extern __shared__ char smem[];
    const uint32_t sb = sa(smem);
    float* bias_s = (float*)(smem + FBIAS);

    const int tid = threadIdx.x;
    const int m0  = blockIdx.x * 64;
    if (tid < 128) { bias_s[tid] = b1[tid]; bias_s[128 + tid] = b2[tid]; }

    const int warp = tid >> 5, lane = tid & 31;
    const int wm = warp & 1, wn = warp >> 1;
    const int grp = lane >> 2, tg = lane & 3;

    const int ar0 = tid >> 3, ac = (tid & 7) * 4;
    const int hr0 = tid >> 2, hu = tid & 3;
    float4 a0, a1;

    // phase 1: Kb=256, chunks 0..3 = LNH fp16 cp.async, 4..7 = RIGHT fp32
    auto ldgAf = [&](int c) {
        if (c < 4 || c >= 8) return;
        int ka = c * 32 - 128;
        int g0 = m0 + ar0, g1 = m0 + ar0 + 32;
        a0 = (g0 < M) ? *(const float4*)(RIGHT + (size_t)g0 * 128 + ka + ac)
                      : make_float4(0.f, 0.f, 0.f, 0.f);
        a1 = (g1 < M) ? *(const float4*)(RIGHT + (size_t)g1 * 128 + ka + ac)
                      : make_float4(0.f, 0.f, 0.f, 0.f);
    };
    auto stsAf = [&](int c, int buf) {
        if (c < 4) return;
        char* base = smem + FA_OFF + buf * 5120;
        __half2 h0 = __floats2half2_rn(a0.x, a0.y), h1 = __floats2half2_rn(a0.z, a0.w);
        *(uint2*)(base + ar0 * 80 + ac * 2) = make_uint2(*(uint32_t*)&h0, *(uint32_t*)&h1);
        __half2 h2 = __floats2half2_rn(a1.x, a1.y), h3 = __floats2half2_rn(a1.z, a1.w);
        *(uint2*)(base + (ar0 + 32) * 80 + ac * 2) = make_uint2(*(uint32_t*)&h2, *(uint32_t*)&h3);
    };
    auto stageAB1 = [&](int c, int buf) {
        if (c < 4) {
            int grow = m0 + hr0;
            int ok = (grow < M);
            cp16(sb + FA_OFF + buf * 5120 + hr0 * 80 + hu * 16,
                 LNH + (size_t)(ok ? grow : 0) * 128 + c * 32 + hu * 8, ok ? 16 : 0);
        }
#pragma unroll
        for (int i = 0; i < 2; i++) {
            int slot = tid + i * 256;
            int r = slot >> 2, u = slot & 3;
            cp16(sb + FB_OFF + buf * 10240 + r * 80 + u * 16,
                 W1T + (size_t)r * 256 + c * 32 + u * 8, 16);
        }
        cp_commit();
    };
    auto stageB2 = [&](int c, int buf) {
#pragma unroll
        for (int i = 0; i < 2; i++) {
            int slot = tid + i * 256;
            int r = slot >> 2, u = slot & 3;
            cp16(sb + FB_OFF + buf * 10240 + r * 80 + u * 16,
                 W2T + (size_t)r * 128 + c * 32 + u * 8, 16);
        }
        cp_commit();
    };

    const uint32_t aOff = (uint32_t)(wm * 32 + (lane & 15)) * 80 + (uint32_t)((lane >> 4) << 3) * 2;
    const uint32_t bOff = (uint32_t)(wn * 32 + (lane & 7) + ((lane >> 4) << 3)) * 80
                        + (uint32_t)(((lane >> 3) & 1) << 3) * 2;

    float acc[2][4][4];
#pragma unroll
    for (int a = 0; a < 2; a++)
#pragma unroll
        for (int b = 0; b < 4; b++)
#pragma unroll
            for (int k = 0; k < 4; k++) acc[a][b][k] = 0.f;

    auto compute = [&](uint32_t abase, int buf) {
        const uint32_t ab = abase + aOff;
        const uint32_t bb = sb + FB_OFF + buf * 10240 + bOff;
#pragma unroll
        for (int ks = 0; ks < 2; ks++) {
            const uint32_t ko = ks * 32;
            uint32_t bfr[8];
            ldm4(&bfr[0], bb + ko);
            ldm4(&bfr[4], bb + 1280 + ko);
            uint32_t afr[4];
            ldm4(afr, ab + ko);
            mma16(acc[0][0], afr, &bfr[0]);
            mma16(acc[0][1], afr, &bfr[2]);
            mma16(acc[0][2], afr, &bfr[4]);
            mma16(acc[0][3], afr, &bfr[6]);
            ldm4(afr, ab + 1280 + ko);
            mma16(acc[1][0], afr, &bfr[0]);
            mma16(acc[1][1], afr, &bfr[2]);
            mma16(acc[1][2], afr, &bfr[4]);
            mma16(acc[1][3], afr, &bfr[6]);
        }
    };

    // ---- phase 1 ----
    ldgAf(0);
    stageAB1(0, 0);
    stsAf(0, 0);
    ldgAf(1);

    for (int c = 0; c < 8; c++) {
        const int buf = c & 1;
        cp_wait0();
        __syncthreads();
        if (c + 1 < 8) stageAB1(c + 1, buf ^ 1);
        compute(sb + FA_OFF + buf * 5120, buf);
        if (c + 1 < 8) {
            stsAf(c + 1, buf ^ 1);
            ldgAf(c + 2);
        }
    }

    // h1 -> smem (relu + b1, fp16), chunk = wn (nt*8+tg*2 < 32)
#pragma unroll
    for (int mt = 0; mt < 2; mt++) {
#pragma unroll
        for (int half = 0; half < 2; half++) {
            int row = wm * 32 + mt * 16 + half * 8 + grp;
#pragma unroll
            for (int nt = 0; nt < 4; nt++) {
                int co = nt * 8 + tg * 2;
                int cc = wn * 32 + co;
                float v0 = fmaxf(acc[mt][nt][half * 2 + 0] + bias_s[cc], 0.f);
                float v1 = fmaxf(acc[mt][nt][half * 2 + 1] + bias_s[cc + 1], 0.f);
                __half2 h = __floats2half2_rn(v0, v1);
                *(uint32_t*)(smem + FH_OFF + wn * 5120 + row * 80 + co * 2) =
                    *(uint32_t*)&h;
            }
        }
    }
    __syncthreads();

    // ---- phase 2: out = h1 @ W2^T + b2 ----
#pragma unroll
    for (int a = 0; a < 2; a++)
#pragma unroll
        for (int b = 0; b < 4; b++)
#pragma unroll
            for (int k = 0; k < 4; k++) acc[a][b][k] = 0.f;

    stageB2(0, 0);
    for (int c = 0; c < 4; c++) {
        const int buf = c & 1;
        cp_wait0();
        __syncthreads();
        if (c + 1 < 4) stageB2(c + 1, buf ^ 1);
        compute(sb + FH_OFF + c * 5120, buf);
    }

#pragma unroll
    for (int mt = 0; mt < 2; mt++) {
#pragma unroll
        for (int half = 0; half < 2; half++) {
            int grow = m0 + wm * 32 + mt * 16 + half * 8 + grp;
            if (grow < M) {
#pragma unroll
                for (int nt = 0; nt < 4; nt++) {
                    int cc = wn * 32 + nt * 8 + tg * 2;
                    float2 o;
                    o.x = acc[mt][nt][half * 2 + 0] + bias_s[128 + cc];
                    o.y = acc[mt][nt][half * 2 + 1] + bias_s[128 + cc + 1];
                    *(float2*)(OUT + (size_t)grow * 128 + cc) = o;
                }
            }
        }
    }
}

// =================================================================
// Edge kernel (R13, unchanged)
// =================================================================
__global__ __launch_bounds__(512, 2) void edge_logits_kernel(
    const float* __restrict__ EF, const __half* __restrict__ WeT,
    const int* __restrict__ src, const int* __restrict__ dst,
    const float* __restrict__ att)
{
    extern __shared__ char smem[];
    const uint32_t sb = sa(smem);
    float* att_s = (float*)(smem + EATT);
    int*   src_s = (int*)(smem + ESRC);
    int*   dst_s = (int*)(smem + EDST);
    const __half* gath = (const __half*)(smem + EGATH);

    const int tid = threadIdx.x;
    const int e0  = blockIdx.x * 128;
    const int warp = tid >> 5, lane = tid & 31;
    const int wm = warp & 3, wn = warp >> 2;
    const int grp = lane >> 2, tg = lane & 3;

    if (tid < 128) {
        src_s[tid] = src[e0 + tid];
        dst_s[tid] = dst[e0 + tid];
        att_s[tid] = att[tid];
    }

    const int ar0 = tid >> 3, ac = (tid & 7) * 4;
    float4 a0, a1;
    auto ldgA = [&](int c) {
        const int ka = c * 32;
        a0 = ldcs4(EF + (size_t)(e0 + ar0) * 128 + ka + ac);
        a1 = ldcs4(EF + (size_t)(e0 + ar0 + 64) * 128 + ka + ac);
    };
    auto stsA = [&](int buf) {
        char* base = smem + EASH + buf * 10240;
        __half2 h0 = __floats2half2_rn(a0.x, a0.y), h1 = __floats2half2_rn(a0.z, a0.w);
        *(uint2*)(base + ar0 * 80 + ac * 2) = make_uint2(*(uint32_t*)&h0, *(uint32_t*)&h1);
        __half2 h2 = __floats2half2_rn(a1.x, a1.y), h3 = __floats2half2_rn(a1.z, a1.w);
        *(uint2*)(base + (ar0 + 64) * 80 + ac * 2) = make_uint2(*(uint32_t*)&h2, *(uint32_t*)&h3);
    };
    const int br = tid >> 2, bu = (tid & 3) * 8;
    auto stageB = [&](int c, int buf) {
        cp16(sb + EBSH + buf * 10240 + br * 80 + bu * 2,
             WeT + (size_t)br * 128 + c * 32 + bu, 16);
        cp_commit();
    };

    const uint32_t aOff = (uint32_t)(wm * 32 + (lane & 15)) * 80 + (uint32_t)((lane >> 4) << 3) * 2;
    const uint32_t bOff = (uint32_t)(wn * 32 + (lane & 7) + ((lane >> 4) << 3)) * 80
                        + (uint32_t)(((lane >> 3) & 1) << 3) * 2;

    float acc[2][4][4];
#pragma unroll
    for (int a = 0; a < 2; a++)
#pragma unroll
        for (int b = 0; b < 4; b++)
#pragma unroll
            for (int k = 0; k < 4; k++) acc[a][b][k] = 0.f;

    auto compute = [&](int buf) {
        const uint32_t ab = sb + EASH + buf * 10240 + aOff;
        const uint32_t bb = sb + EBSH + buf * 10240 + bOff;
#pragma unroll
        for (int ks = 0; ks < 2; ks++) {
            const uint32_t ko = ks * 32;
            uint32_t bfr[8];
            ldm4(&bfr[0], bb + ko);
            ldm4(&bfr[4], bb + 1280 + ko);
            uint32_t afr[4];
            ldm4(afr, ab + ko);
            mma16(acc[0][0], afr, &bfr[0]);
            mma16(acc[0][1], afr, &bfr[2]);
            mma16(acc[0][2], afr, &bfr[4]);
            mma16(acc[0][3], afr, &bfr[6]);
            ldm4(afr, ab + 1280 + ko);
            mma16(acc[1][0], afr, &bfr[0]);
            mma16(acc[1][1], afr, &bfr[2]);
            mma16(acc[1][2], afr, &bfr[4]);
            mma16(acc[1][3], afr, &bfr[6]);
        }
    };

    // ---- prologue ----
    ldgA(0);
    stageB(0, 0);
    stsA(0);
    ldgA(1);

    // chunk 0
    cp_wait0();
    __syncthreads();
    stageB(1, 1);
    {
#pragma unroll
        for (int j = 0; j < 8; j++) {
            int s = tid + 512 * j;
            int row = s >> 4, u = s & 15;
            int idx = row & 127;
            const __half* gp = (j < 4)
                ? g_xlh + (size_t)src_s[idx] * 128 + u * 8
                : g_xrh + (size_t)dst_s[idx] * 128 + u * 8;
            cp16(sb + EGATH + row * 272 + u * 16, gp, 16);
        }
        cp_commit();
    }
    compute(0);
    stsA(1); ldgA(2);

    // chunk 1
    cp_wait1();
    __syncthreads();
    stageB(2, 0);
    compute(1);
    stsA(0); ldgA(3);

    // chunk 2
    cp_wait0();
    __syncthreads();
    stageB(3, 1);
    compute(0);
    stsA(1);

    // chunk 3
    cp_wait0();
    __syncthreads();
    compute(1);

    // ---- epilogue ----
#pragma unroll
    for (int mt = 0; mt < 2; mt++) {
#pragma unroll
        for (int half = 0; half < 2; half++) {
            int row = wm * 32 + mt * 16 + half * 8 + grp;
            const __half* xl = gath + (size_t)row * GSTR;
            const __half* xr = gath + (size_t)(128 + row) * GSTR;
            float partial = 0.f;
#pragma unroll
            for (int nt = 0; nt < 4; nt++) {
                int col = wn * 32 + nt * 8 + tg * 2;
                float2 a = __half22float2(*(const __half2*)(xl + col));
                float2 b = __half22float2(*(const __half2*)(xr + col));
                float z0 = acc[mt][nt][half * 2 + 0] + a.x + b.x;
                float z1 = acc[mt][nt][half * 2 + 1] + a.y + b.y;
                z0 = (z0 > 0.f) ? z0 : 0.2f * z0;
                z1 = (z1 > 0.f) ? z1 : 0.2f * z1;
                partial += z0 * att_s[col] + z1 * att_s[col + 1];
            }
            partial += __shfl_xor_sync(0xFFFFFFFFu, partial, 1);
            partial += __shfl_xor_sync(0xFFFFFFFFu, partial, 2);
            if (tg == 0)
                g_logits[(size_t)(e0 + row) * 4 + wn] = partial;
        }
    }
}

// ---------------- CSR build ----------------
__global__ void count_kernel(const int* __restrict__ dst) {
    int e = blockIdx.x * blockDim.x + threadIdx.x;
    if (e < ENUM) atomicAdd(&g_cnt[dst[e]], 1);
}

__global__ __launch_bounds__(1024) void scan_kernel() {
    __shared__ int part[1024];
    const int t = threadIdx.x;
    const int CH = (NLR + 1023) / 1024;
    int start = t * CH, end = min(start + CH, NLR);
    int s = 0;
    for (int i = start; i < end; i++) s += g_cnt[i];
    part[t] = s;
    __syncthreads();
    for (int off = 1; off < 1024; off <<= 1) {
        int v = (t >= off) ? part[t - off] : 0;
        __syncthreads();
        part[t] += v;
        __syncthreads();
    }
    int run = part[t] - s;
    for (int i = start; i < end; i++) {
        g_off[i] = run; g_cur[i] = run;
        run += g_cnt[i];
    }
    if (t == 1023) g_off[NLR] = part[1023];
}

__global__ void fill_kernel(const int* __restrict__ dst) {
    int e = blockIdx.x * blockDim.x + threadIdx.x;
    if (e < ENUM) {
        int p = atomicAdd(&g_cur[dst[e]], 1);
        g_elist[p] = e;
    }
}

// =================================================================
// Warp-per-node fused segment softmax + message + b_conv + LayerNorm.
// =================================================================
__global__ __launch_bounds__(256) void message_ln_kernel(
    const int* __restrict__ src,
    const float* __restrict__ bconv,
    const float* __restrict__ lng, const float* __restrict__ lnb)
{
    const int node = (blockIdx.x * blockDim.x + threadIdx.x) >> 5;
    const int lane = threadIdx.x & 31;
    if (node >= NLR) return;

    const int h  = lane >> 3;
    const int c4 = lane * 4;
    const int off0 = g_off[node];
    const int deg  = g_off[node + 1] - off0;

    float4 mx = make_float4(-1e30f, -1e30f, -1e30f, -1e30f);
    for (int i = lane; i < deg; i += 32) {
        int e = __ldg(&g_elist[off0 + i]);
        float4 lg = *(const float4*)&g_logits[(size_t)e * 4];
        mx.x = fmaxf(mx.x, lg.x); mx.y = fmaxf(mx.y, lg.y);
        mx.z = fmaxf(mx.z, lg.z); mx.w = fmaxf(mx.w, lg.w);
    }
#pragma unroll
    for (int o = 16; o; o >>= 1) {
        mx.x = fmaxf(mx.x, __shfl_xor_sync(0xFFFFFFFFu, mx.x, o));
        mx.y = fmaxf(mx.y, __shfl_xor_sync(0xFFFFFFFFu, mx.y, o));
        mx.z = fmaxf(mx.z, __shfl_xor_sync(0xFFFFFFFFu, mx.z, o));
        mx.w = fmaxf(mx.w, __shfl_xor_sync(0xFFFFFFFFu, mx.w, o));
    }

    float4 sm = make_float4(0.f, 0.f, 0.f, 0.f);
    for (int i = lane; i < deg; i += 32) {
        int e = __ldg(&g_elist[off0 + i]);
        float4 lg = *(const float4*)&g_logits[(size_t)e * 4];
        sm.x += __expf(lg.x - mx.x); sm.y += __expf(lg.y - mx.y);
        sm.z += __expf(lg.z - mx.z); sm.w += __expf(lg.w - mx.w);
    }
#pragma unroll
    for (int o = 16; o; o >>= 1) {
        sm.x += __shfl_xor_sync(0xFFFFFFFFu, sm.x, o);
        sm.y += __shfl_xor_sync(0xFFFFFFFFu, sm.y, o);
        sm.z += __shfl_xor_sync(0xFFFFFFFFu, sm.z, o);
        sm.w += __shfl_xor_sync(0xFFFFFFFFu, sm.w, o);
    }

    const float m_h = (h == 0) ? mx.x : (h == 1) ? mx.y : (h == 2) ? mx.z : mx.w;
    const float s_h = (h == 0) ? sm.x : (h == 1) ? sm.y : (h == 2) ? sm.z : sm.w;
    const float inv_h = 1.f / (s_h + 1e-16f);

    float4 acc = make_float4(0.f, 0.f, 0.f, 0.f);
    int j = 0;
    for (; j + 1 < deg; j += 2) {
        int e0v = __ldg(&g_elist[off0 + j]);
        int e1v = __ldg(&g_elist[off0 + j + 1]);
        int s0 = __ldg(&src[e0v]);
        int s1 = __ldg(&src[e1v]);
        float a0 = __expf(__ldg(&g_logits[(size_t)e0v * 4 + h]) - m_h);
        float a1 = __expf(__ldg(&g_logits[(size_t)e1v * 4 + h]) - m_h);
        const __half2* x0 = (const __half2*)(g_xlh + (size_t)s0 * 128 + c4);
        const __half2* x1 = (const __half2*)(g_xlh + (size_t)s1 * 128 + c4);
        float2 p00 = __half22float2(x0[0]), p01 = __half22float2(x0[1]);
        float2 p10 = __half22float2(x1[0]), p11 = __half22float2(x1[1]);
        acc.x = fmaf(a0, p00.x, fmaf(a1, p10.x, acc.x));
        acc.y = fmaf(a0, p00.y, fmaf(a1, p10.y, acc.y));
        acc.z = fmaf(a0, p01.x, fmaf(a1, p11.x, acc.z));
        acc.w = fmaf(a0, p01.y, fmaf(a1, p11.y, acc.w));
    }
    if (j < deg) {
        int e = __ldg(&g_elist[off0 + j]);
        int sr = __ldg(&src[e]);
        float a = __expf(__ldg(&g_logits[(size_t)e * 4 + h]) - m_h);
        const __half2* xp = (const __half2*)(g_xlh + (size_t)sr * 128 + c4);
        float2 x01 = __half22float2(xp[0]);
        float2 x23 = __half22float2(xp[1]);
        acc.x = fmaf(a, x01.x, acc.x); acc.y = fmaf(a, x01.y, acc.y);
        acc.z = fmaf(a, x23.x, acc.z); acc.w = fmaf(a, x23.y, acc.w);
    }
    float4 bc = *(const float4*)&bconv[c4];
    float4 msg;
    msg.x = acc.x * inv_h + bc.x; msg.y = acc.y * inv_h + bc.y;
    msg.z = acc.z * inv_h + bc.z; msg.w = acc.w * inv_h + bc.w;

    float s1 = msg.x + msg.y + msg.z + msg.w;
    float s2 = msg.x * msg.x + msg.y * msg.y + msg.z * msg.z + msg.w * msg.w;
#pragma unroll
    for (int o = 16; o; o >>= 1) {
        s1 += __shfl_xor_sync(0xFFFFFFFFu, s1, o);
        s2 += __shfl_xor_sync(0xFFFFFFFFu, s2, o);
    }
    float mu  = s1 * (1.f / 128.f);
    float var = fmaxf(s2 * (1.f / 128.f) - mu * mu, 0.f);
    float r = rsqrtf(var + 1e-5f);

    float4 g = *(const float4*)&lng[c4];
    float4 b = *(const float4*)&lnb[c4];
    __half2 o0 = __floats2half2_rn((msg.x - mu) * r * g.x + b.x,
                                   (msg.y - mu) * r * g.y + b.y);
    __half2 o1 = __floats2half2_rn((msg.z - mu) * r * g.z + b.z,
                                   (msg.w - mu) * r * g.w + b.w);
    *(uint2*)&g_lnh[(size_t)node * 128 + c4] =
        make_uint2(*(uint32_t*)&o0, *(uint32_t*)&o1);
}

// =================================================================
extern "C" void kernel_launch(void* const* d_in, const int* in_sizes, int n_in,
                              void* d_out, int out_size) {
    const float* left  = (const float*)d_in[0];
    const int*   eidx  = (const int*)d_in[1];
    const float* ef    = (const float*)d_in[2];
    const float* right = (const float*)d_in[3];
    const float* W_l   = (const float*)d_in[4];
    const float* b_l   = (const float*)d_in[5];
    const float* W_r   = (const float*)d_in[6];
    const float* b_r   = (const float*)d_in[7];
    const float* W_e   = (const float*)d_in[8];
    const float* att   = (const float*)d_in[9];
    const float* bconv = (const float*)d_in[10];
    const float* ln_g  = (const float*)d_in[11];
    const float* ln_b  = (const float*)d_in[12];
    const float* W1    = (const float*)d_in[13];
    const float* b1    = (const float*)d_in[14];
    const float* W2    = (const float*)d_in[15];
    const float* b2    = (const float*)d_in[16];
    float* out = (float*)d_out;

    const int* src = eidx;
    const int* dst = eidx + ENUM;

    __half* lnh; cudaGetSymbolAddress((void**)&lnh, g_lnh);
    __half* wTh; cudaGetSymbolAddress((void**)&wTh, g_wTh);
    int*    cnt; cudaGetSymbolAddress((void**)&cnt, g_cnt);

    cudaFuncSetAttribute(gemm_dual,
                         cudaFuncAttributeMaxDynamicSharedMemorySize, SMEM_GEMM);
    cudaFuncSetAttribute(mlp_fused,
                         cudaFuncAttributeMaxDynamicSharedMemorySize, SMEM_FUSED);
    cudaFuncSetAttribute(edge_logits_kernel,
                         cudaFuncAttributeMaxDynamicSharedMemorySize, SMEM_EDGE2);

    const int gblk = (NLR + 63) / 64;   // 782 (64-row tiles)

    // side stream for the CSR branch (independent of the GEMM chain)
    cudaStream_t s2;
    cudaStreamCreateWithFlags(&s2, cudaStreamNonBlocking);
    cudaEvent_t evFork, evJoin;
    cudaEventCreateWithFlags(&evFork, cudaEventDisableTiming);
    cudaEventCreateWithFlags(&evJoin, cudaEventDisableTiming);

    cudaEventRecord(evFork, 0);
    cudaStreamWaitEvent(s2, evFork, 0);

    cudaMemsetAsync(cnt, 0, NLR * sizeof(int), s2);

    transpose5<<<96, dim3(32, 8)>>>(W_l, W_r, W_e, W1, W2);                  // k1
    count_kernel<<<(ENUM + 255) / 256, 256, 0, s2>>>(dst);                   // k2
    gemm_dual<<<2 * gblk, 256, SMEM_GEMM>>>(left, wTh + WL_T, b_l,
                                            right, wTh + WR_T, b_r,
                                            NLR, gblk);                      // k3
    edge_logits_kernel<<<ENUM / 128, 512, SMEM_EDGE2>>>(ef, wTh + WE_T,
                                                        src, dst, att);      // k4 (profiled)
    scan_kernel<<<1, 1024, 0, s2>>>();                                       // k5
    fill_kernel<<<(ENUM + 255) / 256, 256, 0, s2>>>(dst);                    // k6

    cudaEventRecord(evJoin, s2);
    cudaStreamWaitEvent(0, evJoin, 0);

    message_ln_kernel<<<(NLR * 32 + 255) / 256, 256>>>(src, bconv, ln_g, ln_b); // k7
    // fused MLP: out = (relu([lnh|right] @ W1 + b1)) @ W2 + b2
    mlp_fused<<<gblk, 256, SMEM_FUSED>>>(lnh, right, wTh + W1_T, wTh + W2_T,
                                         b1, b2, out, NLR);                  // k8
}